// round 7
// baseline (speedup 1.0000x reference)
#include <cuda_runtime.h>
#include <cstdint>

#define BATCH    64
#define NB       2            // batches per CTA
#define SEQ      8192
#define RDIM     80
#define NTAPS    5
#define MAXD     168
#define RING     169
#define NTHREADS 320          // i = tid % 80, jh = tid / 80
#define JSLICE   20
#define NPAIR    10

typedef unsigned long long u64;

__device__ __forceinline__ u64 ffma2(u64 a, u64 b, u64 c) {
    u64 d;
    asm("fma.rn.f32x2 %0, %1, %2, %3;" : "=l"(d) : "l"(a), "l"(b), "l"(c));
    return d;
}

__device__ __forceinline__ float2 unpack2(u64 v) {
    unsigned lo, hi;
    asm("mov.b64 {%0, %1}, %2;" : "=r"(lo), "=r"(hi) : "l"(v));
    float2 r;
    r.x = __uint_as_float(lo);
    r.y = __uint_as_float(hi);
    return r;
}

__device__ __forceinline__ float fast_tanh(float v) {
    v = fminf(fmaxf(v, -15.0f), 15.0f);
    float u = __expf(-2.0f * v);
    return __fdividef(1.0f - u, 1.0f + u);
}

// Accumulate one tap row (20 floats at hrow) against Wp[k][*] into a0..a3 (suffix g)
#define TAP_ACC(k, hrow, a0, a1, a2, a3)                                  \
    do {                                                                  \
        const ulonglong2* hv = reinterpret_cast<const ulonglong2*>(hrow); \
        ulonglong2 h01 = hv[0];                                           \
        ulonglong2 h23 = hv[1];                                           \
        ulonglong2 h45 = hv[2];                                           \
        ulonglong2 h67 = hv[3];                                           \
        ulonglong2 h89 = hv[4];                                           \
        a0 = ffma2(h01.x, Wp[k][0], a0);                                  \
        a1 = ffma2(h01.y, Wp[k][1], a1);                                  \
        a2 = ffma2(h23.x, Wp[k][2], a2);                                  \
        a3 = ffma2(h23.y, Wp[k][3], a3);                                  \
        a0 = ffma2(h45.x, Wp[k][4], a0);                                  \
        a1 = ffma2(h45.y, Wp[k][5], a1);                                  \
        a2 = ffma2(h67.x, Wp[k][6], a2);                                  \
        a3 = ffma2(h67.y, Wp[k][7], a3);                                  \
        a0 = ffma2(h89.x, Wp[k][8], a0);                                  \
        a1 = ffma2(h89.y, Wp[k][9], a1);                                  \
    } while (0)

__global__ __launch_bounds__(NTHREADS, 1)
void reservoir_kernel(const float* __restrict__ x,
                      const float* __restrict__ Win,
                      const float* __restrict__ Wfb,
                      const float* __restrict__ bias,
                      float* __restrict__ out)
{
    extern __shared__ float sm[];
    float* Hring0 = sm;                          // [RING][RDIM]
    float* Hring1 = Hring0 + RING * RDIM;        // [RING][RDIM]
    float* xs0    = Hring1 + RING * RDIM;        // [SEQ]
    float* xs1    = xs0 + SEQ;                   // [SEQ]
    float* part0  = xs1 + SEQ;                   // [2][NTHREADS]
    float* part1  = part0 + 2 * NTHREADS;        // [2][NTHREADS]

    const int tid = threadIdx.x;
    const int i   = tid % RDIM;   // neuron index for tap work
    const int jh  = tid / RDIM;   // j-quarter 0..3

    const int b0 = 2 * blockIdx.x;
    const int b1 = b0 + 1;

    for (int idx = tid; idx < RING * RDIM; idx += NTHREADS) {
        Hring0[idx] = 0.0f;
        Hring1[idx] = 0.0f;
    }
    const float* xb0 = x + (size_t)b0 * SEQ;
    const float* xb1 = x + (size_t)b1 * SEQ;
    for (int idx = tid; idx < SEQ; idx += NTHREADS) {
        xs0[idx] = xb0[idx];
        xs1[idx] = xb1[idx];
    }

    // W_fb slice in registers — SHARED across both batches.
    u64 Wp[NTAPS][NPAIR];
#pragma unroll
    for (int k = 0; k < NTAPS; k++) {
        const float* wrow = Wfb + ((size_t)k * RDIM + i) * RDIM + jh * JSLICE;
#pragma unroll
        for (int p = 0; p < NPAIR; p++) {
            unsigned lo = __float_as_uint(wrow[2 * p]);
            unsigned hi = __float_as_uint(wrow[2 * p + 1]);
            Wp[k][p] = ((u64)hi << 32) | (u64)lo;
        }
    }

    // Epilogue identity: threads 0..159, g = tid/80 (batch), e = tid%80 (neuron)
    const int eg = tid / RDIM;            // 0 or 1 for tid<160
    const int ei = tid % RDIM;
    float win_e = 0.0f, bias_e = 0.0f, h_e = 0.0f;
    if (tid < 2 * RDIM) { win_e = Win[ei]; bias_e = bias[ei]; }

    float* outb0 = out + (size_t)b0 * SEQ * RDIM;
    float* outb1 = out + (size_t)b1 * SEQ * RDIM;

    const float* hb0 = Hring0 + jh * JSLICE;
    const float* hb1 = Hring1 + jh * JSLICE;

    // Ring slots at t=0: write w=0; reads r_k = (0 - tau_k) mod 169
    int w  = 0;
    int r0 = RING - 1;    // tau 1
    int r1 = RING - 4;    // tau 4
    int r2 = RING - 24;   // tau 24
    int r3 = RING - 96;   // tau 96
    int r4 = RING - 168;  // tau 168

    __syncthreads();

#pragma unroll 1
    for (int t = 0; t < SEQ; ++t) {
        u64 p0 = 0ull, p1 = 0ull, p2 = 0ull, p3 = 0ull;   // batch 0 acc
        u64 q0 = 0ull, q1 = 0ull, q2 = 0ull, q3 = 0ull;   // batch 1 acc

        // ---- P1: old taps (4,24,96,168) for BOTH batches. The two
        // independent streams interleave, hiding LDS/FFMA latency.
        TAP_ACC(1, hb0 + r1 * RDIM, p0, p1, p2, p3);
        TAP_ACC(1, hb1 + r1 * RDIM, q0, q1, q2, q3);
        TAP_ACC(2, hb0 + r2 * RDIM, p0, p1, p2, p3);
        TAP_ACC(2, hb1 + r2 * RDIM, q0, q1, q2, q3);
        TAP_ACC(3, hb0 + r3 * RDIM, p0, p1, p2, p3);
        TAP_ACC(3, hb1 + r3 * RDIM, q0, q1, q2, q3);
        TAP_ACC(4, hb0 + r4 * RDIM, p0, p1, p2, p3);
        TAP_ACC(4, hb1 + r4 * RDIM, q0, q1, q2, q3);

        // ---- BAR A: h[t-1] of both batches visible.
        __syncthreads();

        // ---- P2: tau=1 for both batches.
        TAP_ACC(0, hb0 + r0 * RDIM, p0, p1, p2, p3);
        TAP_ACC(0, hb1 + r0 * RDIM, q0, q1, q2, q3);

        {
            float2 f0 = unpack2(p0);
            float2 f1 = unpack2(p1);
            float2 f2 = unpack2(p2);
            float2 f3 = unpack2(p3);
            part0[(t & 1) * NTHREADS + tid] =
                ((f0.x + f0.y) + (f1.x + f1.y)) + ((f2.x + f2.y) + (f3.x + f3.y));
            float2 g0 = unpack2(q0);
            float2 g1 = unpack2(q1);
            float2 g2 = unpack2(q2);
            float2 g3 = unpack2(q3);
            part1[(t & 1) * NTHREADS + tid] =
                ((g0.x + g0.y) + (g1.x + g1.y)) + ((g2.x + g2.y) + (g3.x + g3.y));
        }

        // ---- BAR B: partials visible.
        __syncthreads();

        // ---- Epilogue: 160 threads, one (batch, neuron) each — parallel.
        if (tid < 2 * RDIM) {
            const float* pb = (eg == 0 ? part0 : part1) + (t & 1) * NTHREADS;
            float f = (pb[ei] + pb[ei + RDIM]) +
                      (pb[ei + 2 * RDIM] + pb[ei + 3 * RDIM]);
            const float* xst = (eg == 0) ? xs0 : xs1;
            float val = fmaf(xst[t], win_e, f + bias_e);
            h_e = 0.7f * h_e + 0.3f * fast_tanh(val);
            float* hr = (eg == 0) ? Hring0 : Hring1;
            hr[w * RDIM + ei] = h_e;
            float* ob = (eg == 0) ? outb0 : outb1;
            ob[(size_t)t * RDIM + ei] = h_e;
        }

        ++w;  if (w  == RING) w  = 0;
        ++r0; if (r0 == RING) r0 = 0;
        ++r1; if (r1 == RING) r1 = 0;
        ++r2; if (r2 == RING) r2 = 0;
        ++r3; if (r3 == RING) r3 = 0;
        ++r4; if (r4 == RING) r4 = 0;
    }
}

extern "C" void kernel_launch(void* const* d_in, const int* in_sizes, int n_in,
                              void* d_out, int out_size)
{
    const float* x    = (const float*)d_in[0];  // [64, 8192, 1]
    const float* Win  = (const float*)d_in[1];  // [80, 1]
    const float* Wfb  = (const float*)d_in[2];  // [5, 80, 80]
    const float* bias = (const float*)d_in[3];  // [80]
    float* out = (float*)d_out;                 // [64, 8192, 80]

    const int smem_bytes =
        (NB * RING * RDIM + NB * SEQ + NB * 2 * NTHREADS) * sizeof(float);
    cudaFuncSetAttribute(reservoir_kernel,
                         cudaFuncAttributeMaxDynamicSharedMemorySize, smem_bytes);

    reservoir_kernel<<<BATCH / NB, NTHREADS, smem_bytes>>>(x, Win, Wfb, bias, out);
}

// round 8
// speedup vs baseline: 1.7109x; 1.7109x over previous
#include <cuda_runtime.h>
#include <cstdint>

#define BATCH    64
#define SEQ      8192
#define RDIM     80
#define NTAPS    5
#define MAXD     168
#define RING     169          // write slot disjoint from all read slots mod 169
#define NTHREADS 320          // i = tid % 80, jh = tid / 80
#define JSLICE   20
#define NPAIR    10

typedef unsigned long long u64;

__device__ __forceinline__ u64 ffma2(u64 a, u64 b, u64 c) {
    u64 d;
    asm("fma.rn.f32x2 %0, %1, %2, %3;" : "=l"(d) : "l"(a), "l"(b), "l"(c));
    return d;
}

__device__ __forceinline__ float2 unpack2(u64 v) {
    unsigned lo, hi;
    asm("mov.b64 {%0, %1}, %2;" : "=r"(lo), "=r"(hi) : "l"(v));
    float2 r;
    r.x = __uint_as_float(lo);
    r.y = __uint_as_float(hi);
    return r;
}

__device__ __forceinline__ float fast_tanh(float v) {
    v = fminf(fmaxf(v, -15.0f), 15.0f);
    float u = __expf(-2.0f * v);
    return __fdividef(1.0f - u, 1.0f + u);
}

#define BAR_SYNC_B()   asm volatile("bar.sync 1, %0;"   :: "n"(NTHREADS) : "memory")
#define BAR_ARRIVE_B() asm volatile("bar.arrive 1, %0;" :: "n"(NTHREADS) : "memory")

// Accumulate one tap row (20 floats at hrow) against Wp[k][*]
#define TAP_ACC(k, hrow)                                                  \
    do {                                                                  \
        const ulonglong2* hv = reinterpret_cast<const ulonglong2*>(hrow); \
        ulonglong2 h01 = hv[0];                                           \
        ulonglong2 h23 = hv[1];                                           \
        ulonglong2 h45 = hv[2];                                           \
        ulonglong2 h67 = hv[3];                                           \
        ulonglong2 h89 = hv[4];                                           \
        a0 = ffma2(h01.x, Wp[k][0], a0);                                  \
        a1 = ffma2(h01.y, Wp[k][1], a1);                                  \
        a2 = ffma2(h23.x, Wp[k][2], a2);                                  \
        a3 = ffma2(h23.y, Wp[k][3], a3);                                  \
        a0 = ffma2(h45.x, Wp[k][4], a0);                                  \
        a1 = ffma2(h45.y, Wp[k][5], a1);                                  \
        a2 = ffma2(h67.x, Wp[k][6], a2);                                  \
        a3 = ffma2(h67.y, Wp[k][7], a3);                                  \
        a0 = ffma2(h89.x, Wp[k][8], a0);                                  \
        a1 = ffma2(h89.y, Wp[k][9], a1);                                  \
    } while (0)

__global__ __launch_bounds__(NTHREADS, 1)
void reservoir_kernel(const float* __restrict__ x,
                      const float* __restrict__ Win,
                      const float* __restrict__ Wfb,
                      const float* __restrict__ bias,
                      float* __restrict__ out)
{
    extern __shared__ float sm[];
    float* Hring = sm;                     // [RING][RDIM] = 13520 f
    float* xs    = Hring + RING * RDIM;    // [SEQ]        = 8192 f
    float* part  = xs + SEQ;               // [NTHREADS]   = 320 f (single buffer)

    const int b   = blockIdx.x;
    const int tid = threadIdx.x;
    const int i   = tid % RDIM;   // neuron index
    const int jh  = tid / RDIM;   // j-quarter 0..3
    const int wid = tid >> 5;     // warp id; warps 0-2 = epilogue group

    for (int idx = tid; idx < RING * RDIM; idx += NTHREADS) Hring[idx] = 0.0f;

    const float* xb = x + (size_t)b * SEQ;
    for (int idx = tid; idx < SEQ; idx += NTHREADS) xs[idx] = xb[idx];

    // feedback[i] = sum_k sum_j delayed[k][j] * Wfb[k][i][j]
    u64 Wp[NTAPS][NPAIR];
#pragma unroll
    for (int k = 0; k < NTAPS; k++) {
        const float* wrow = Wfb + ((size_t)k * RDIM + i) * RDIM + jh * JSLICE;
#pragma unroll
        for (int p = 0; p < NPAIR; p++) {
            unsigned lo = __float_as_uint(wrow[2 * p]);
            unsigned hi = __float_as_uint(wrow[2 * p + 1]);
            Wp[k][p] = ((u64)hi << 32) | (u64)lo;
        }
    }

    float win_i = 0.0f, bias_i = 0.0f, h_i = 0.0f;
    if (tid < RDIM) { win_i = Win[tid]; bias_i = bias[tid]; }

    float* outb = out + (size_t)b * SEQ * RDIM;
    const float* hbase = Hring + jh * JSLICE;

    // Ring slots at t=0: write w=0; reads r_k = (0 - tau_k) mod 169
    int w  = 0;
    int r0 = RING - 1;    // tau 1
    int r1 = RING - 4;    // tau 4
    int r2 = RING - 24;   // tau 24
    int r3 = RING - 96;   // tau 96
    int r4 = RING - 168;  // tau 168

    __syncthreads();

#pragma unroll 1
    for (int t = 0; t < SEQ; ++t) {
        u64 a0 = 0ull, a1 = 0ull, a2 = 0ull, a3 = 0ull;

        // ---- P1: old taps {4,24,96,168} — need only h[t-4] and older
        // (visible since BAR A of step t-3). Producer warps issue this
        // while epilogue warps of step t-1 are still in their tail.
        TAP_ACC(1, hbase + r1 * RDIM);
        TAP_ACC(2, hbase + r2 * RDIM);
        TAP_ACC(3, hbase + r3 * RDIM);
        TAP_ACC(4, hbase + r4 * RDIM);

        const float x_t = xs[t];

        // ---- BAR A (full): h[t-1] (stored by epilogue of t-1) visible.
        __syncthreads();

        // ---- P2: tau=1 (needs h[t-1]) + partial store
        TAP_ACC(0, hbase + r0 * RDIM);

        float2 f0 = unpack2(a0);
        float2 f1 = unpack2(a1);
        float2 f2 = unpack2(a2);
        float2 f3 = unpack2(a3);
        // layout part[i*4 + jh] -> epilogue reads one float4 per neuron
        part[i * 4 + jh] =
            ((f0.x + f0.y) + (f1.x + f1.y)) + ((f2.x + f2.y) + (f3.x + f3.y));

        if (wid < 3) {
            // ---- consumer warps: wait for all partials, run epilogue
            BAR_SYNC_B();
            if (tid < RDIM) {
                float4 p4 = *reinterpret_cast<const float4*>(part + 4 * tid);
                float f = (p4.x + p4.y) + (p4.z + p4.w);
                float val = fmaf(x_t, win_i, f + bias_i);
                h_i = 0.7f * h_i + 0.3f * fast_tanh(val);
                Hring[w * RDIM + tid] = h_i;           // slot t
                outb[(size_t)t * RDIM + tid] = h_i;
            }
        } else {
            // ---- producer warps: non-blocking arrive, go fetch step t+1
            BAR_ARRIVE_B();
        }

        ++w;  if (w  == RING) w  = 0;
        ++r0; if (r0 == RING) r0 = 0;
        ++r1; if (r1 == RING) r1 = 0;
        ++r2; if (r2 == RING) r2 = 0;
        ++r3; if (r3 == RING) r3 = 0;
        ++r4; if (r4 == RING) r4 = 0;
        // Single-buffer partials are safe: producers write part[] for t+1
        // only after BAR A(t+1), which epilogue warps reach only after
        // having consumed part[] for t.
    }
}

extern "C" void kernel_launch(void* const* d_in, const int* in_sizes, int n_in,
                              void* d_out, int out_size)
{
    const float* x    = (const float*)d_in[0];  // [64, 8192, 1]
    const float* Win  = (const float*)d_in[1];  // [80, 1]
    const float* Wfb  = (const float*)d_in[2];  // [5, 80, 80]
    const float* bias = (const float*)d_in[3];  // [80]
    float* out = (float*)d_out;                 // [64, 8192, 80]

    const int smem_bytes = (RING * RDIM + SEQ + NTHREADS) * sizeof(float);
    cudaFuncSetAttribute(reservoir_kernel,
                         cudaFuncAttributeMaxDynamicSharedMemorySize, smem_bytes);

    reservoir_kernel<<<BATCH, NTHREADS, smem_bytes>>>(x, Win, Wfb, bias, out);
}